// round 6
// baseline (speedup 1.0000x reference)
#include <cuda_runtime.h>

// StrictOrthogonal via Cholesky-QR:
//   G = X^H X        (32x32 complex Hermitian, split-K partials, deterministic)
//   G = R^H R        (sqrt-free Cholesky, fused with fp64 reduce + W = R^{-1})
//   Q = X W          (triangular GEMM, fully parallel, no serial chain)

#define MROWS 16384
#define RCOLS 32
#define GB 128                        // gram split-K blocks
#define ROWS_PER_BLOCK (MROWS / GB)   // 128

__device__ float2 g_partials[GB][RCOLS * RCOLS];
__device__ float2 g_W[RCOLS * RCOLS];   // W = R^{-1} (upper triangular, incl. diag)

// ---------------------------------------------------------------------------
// Kernel 1: per-block partial Gram.  Block b handles rows [b*128, b*128+128).
// 256 threads = 4 K-groups x 64 threads; each thread owns a 4x4 complex tile,
// accumulating over its 32 rows from SMEM (SoA planes, float4 loads).
// ---------------------------------------------------------------------------
__global__ void __launch_bounds__(256) gram_kernel(const float* __restrict__ x) {
    __shared__ float4 sbuf4[2048];                 // 32KB
    float*  s_re = reinterpret_cast<float*>(sbuf4);                    // [128][32]
    float*  s_im = s_re + ROWS_PER_BLOCK * RCOLS;                      // [128][32]
    float2* red  = reinterpret_cast<float2*>(sbuf4);                   // 4096 float2

    const int b = blockIdx.x;
    const float4* __restrict__ xr4 =
        reinterpret_cast<const float4*>(x) + (size_t)b * ROWS_PER_BLOCK * (RCOLS / 2);

    // coalesced float4 load of the 128x32 complex tile, split into re/im planes
    for (int t = threadIdx.x; t < ROWS_PER_BLOCK * (RCOLS / 2); t += 256) {
        float4 v = xr4[t];                 // two complex values
        s_re[2 * t]     = v.x;  s_im[2 * t]     = v.y;
        s_re[2 * t + 1] = v.z;  s_im[2 * t + 1] = v.w;
    }
    __syncthreads();

    const int t  = threadIdx.x;
    const int g  = t >> 6;          // K-group 0..3 (rows r == g mod 4)
    const int u  = t & 63;
    const int i0 = (u >> 3) * 4;    // 0,4,...,28
    const int j0 = (u & 7) * 4;     // 0,4,...,28

    float accx[4][4], accy[4][4];
    #pragma unroll
    for (int p = 0; p < 4; p++)
        #pragma unroll
        for (int q = 0; q < 4; q++) { accx[p][q] = 0.f; accy[p][q] = 0.f; }

    for (int r = g; r < ROWS_PER_BLOCK; r += 4) {
        const float* rr = s_re + r * RCOLS;
        const float* ri = s_im + r * RCOLS;
        float4 arx = *reinterpret_cast<const float4*>(rr + i0);
        float4 ary = *reinterpret_cast<const float4*>(ri + i0);
        float4 brx = *reinterpret_cast<const float4*>(rr + j0);
        float4 bry = *reinterpret_cast<const float4*>(ri + j0);
        const float ax[4] = {arx.x, arx.y, arx.z, arx.w};
        const float ay[4] = {ary.x, ary.y, ary.z, ary.w};
        const float bx[4] = {brx.x, brx.y, brx.z, brx.w};
        const float by[4] = {bry.x, bry.y, bry.z, bry.w};
        #pragma unroll
        for (int p = 0; p < 4; p++)
            #pragma unroll
            for (int q = 0; q < 4; q++) {
                // acc += conj(a_p) * b_q
                accx[p][q] = fmaf(ax[p], bx[q], accx[p][q]);
                accx[p][q] = fmaf(ay[p], by[q], accx[p][q]);
                accy[p][q] = fmaf(ax[p], by[q], accy[p][q]);
                accy[p][q] = fmaf(-ay[p], bx[q], accy[p][q]);
            }
    }
    __syncthreads();   // tile reads done; reuse smem as reduction buffer

    #pragma unroll
    for (int p = 0; p < 4; p++)
        #pragma unroll
        for (int q = 0; q < 4; q++)
            red[g * 1024 + (i0 + p) * 32 + (j0 + q)] = make_float2(accx[p][q], accy[p][q]);
    __syncthreads();

    for (int e = t; e < 1024; e += 256) {
        float2 s0 = red[e], s1 = red[1024 + e], s2 = red[2048 + e], s3 = red[3072 + e];
        g_partials[b][e] = make_float2(s0.x + s1.x + s2.x + s3.x,
                                       s0.y + s1.y + s2.y + s3.y);
    }
}

// ---------------------------------------------------------------------------
// Kernel 2 (fused): fp64 reduce of partials -> Cholesky -> W = R^{-1}.
// One block of 1024 threads, thread t = (i = t>>5, j = t&31).
//  - reduce: 4 interleaved fp64 accumulators (short dependency chains)
//  - Cholesky: sqrt-free right-looking, 1 barrier per k-step
//  - back-substitution R W = I: right-looking, 1 barrier per k-step
// ---------------------------------------------------------------------------
__global__ void __launch_bounds__(1024) cholw_kernel() {
    __shared__ float2 Gs[RCOLS][RCOLS + 1];
    __shared__ float2 Rs[RCOLS][RCOLS];
    __shared__ float2 Bs[RCOLS][RCOLS + 1];
    const int t = threadIdx.x;
    const int i = t >> 5, j = t & 31;

    // --- fp64 deterministic reduce of 128 partials for entry t ---
    double sx0 = 0, sx1 = 0, sx2 = 0, sx3 = 0;
    double sy0 = 0, sy1 = 0, sy2 = 0, sy3 = 0;
    #pragma unroll 4
    for (int b = 0; b < GB; b += 4) {
        float2 p0 = g_partials[b][t],     p1 = g_partials[b + 1][t];
        float2 p2 = g_partials[b + 2][t], p3 = g_partials[b + 3][t];
        sx0 += p0.x; sy0 += p0.y;
        sx1 += p1.x; sy1 += p1.y;
        sx2 += p2.x; sy2 += p2.y;
        sx3 += p3.x; sy3 += p3.y;
    }
    Gs[i][j] = make_float2((float)((sx0 + sx1) + (sx2 + sx3)),
                           (float)((sy0 + sy1) + (sy2 + sy3)));
    Bs[i][j] = make_float2((i == j) ? 1.f : 0.f, 0.f);
    __syncthreads();

    // --- sqrt-free Cholesky (lower triangle), 1 barrier per step ---
    #pragma unroll 1
    for (int k = 0; k < RCOLS; k++) {
        const float invg = 1.f / Gs[k][k].x;
        if (i > k && j > k && j <= i) {
            float2 a = Gs[i][k], c = Gs[j][k];
            float pr = a.x * c.x + a.y * c.y;    // (a * conj(c)).re
            float pi = a.y * c.x - a.x * c.y;    // (a * conj(c)).im
            Gs[i][j].x -= pr * invg;
            Gs[i][j].y -= pi * invg;
        }
        __syncthreads();
    }

    // --- build R (upper): R[i][j] = conj(Gs[j][i]) * rsqrt(D_i), R[i][i]=sqrt(D_i)
    float2 rv = make_float2(0.f, 0.f);
    if (j > i) {
        float2 l = Gs[j][i];
        float  s = rsqrtf(Gs[i][i].x);
        rv = make_float2(l.x * s, -l.y * s);
    } else if (j == i) {
        rv = make_float2(sqrtf(Gs[i][i].x), 0.f);
    }
    Rs[i][j] = rv;
    __syncthreads();

    // --- back-substitution: solve R W = I (W upper incl. diag), 1 barrier/step.
    // Step k: w[k][j] = Bs[k][j] / R[k][k]  (R[k][k] real > 0);
    //         Bs[i][j] -= R[i][k] * w[k][j] for i < k.
    // No thread writes Bs row k during step k (safe single barrier).
    #pragma unroll 1
    for (int k = RCOLS - 1; k >= 0; k--) {
        const float inv = 1.f / Rs[k][k].x;
        float2 bk = Bs[k][j];                       // smem broadcast per column j
        float2 w  = make_float2(bk.x * inv, bk.y * inv);
        if (i == k)
            g_W[k * RCOLS + j] = (j >= k) ? w : make_float2(0.f, 0.f);
        if (i < k) {
            float2 r = Rs[i][k];
            Bs[i][j].x -= r.x * w.x - r.y * w.y;
            Bs[i][j].y -= r.x * w.y + r.y * w.x;
        }
        __syncthreads();
    }
}

// ---------------------------------------------------------------------------
// Kernel 3: Q = X * W  (W upper triangular).  One thread per row, x row in
// registers, W broadcast from SMEM via uniform float4 loads.  Outputs computed
// in groups of 4 columns -> 8 independent accumulator chains, no serial dep.
// ---------------------------------------------------------------------------
__global__ void __launch_bounds__(64) apply_kernel(const float* __restrict__ x,
                                                   float* __restrict__ out) {
    __shared__ __align__(16) float2 Ws[RCOLS][RCOLS];
    const int t = threadIdx.x;
    for (int e = t; e < RCOLS * RCOLS; e += 64)
        Ws[e >> 5][e & 31] = g_W[e];
    __syncthreads();

    const int row = blockIdx.x * 64 + t;
    const float4* __restrict__ src = reinterpret_cast<const float4*>(x) + (size_t)row * 16;
    float4* __restrict__ dst = reinterpret_cast<float4*>(out) + (size_t)row * 16;

    float2 v[RCOLS];
    #pragma unroll
    for (int q = 0; q < 16; q++) {
        float4 f = src[q];
        v[2 * q]     = make_float2(f.x, f.y);
        v[2 * q + 1] = make_float2(f.z, f.w);
    }

    #pragma unroll
    for (int g = 0; g < 8; g++) {
        float ax0 = 0.f, ay0 = 0.f, ax1 = 0.f, ay1 = 0.f;
        float ax2 = 0.f, ay2 = 0.f, ax3 = 0.f, ay3 = 0.f;
        #pragma unroll
        for (int ii = 0; ii < 4 * g + 4; ii++) {   // triangular: W[ii][j]=0 for ii>j
            const float2 a = v[ii];
            const float4* wp = reinterpret_cast<const float4*>(&Ws[ii][4 * g]);
            const float4 w01 = wp[0];              // (W[ii][4g], W[ii][4g+1])
            const float4 w23 = wp[1];              // (W[ii][4g+2], W[ii][4g+3])
            ax0 = fmaf(a.x, w01.x, ax0); ax0 = fmaf(-a.y, w01.y, ax0);
            ay0 = fmaf(a.x, w01.y, ay0); ay0 = fmaf( a.y, w01.x, ay0);
            ax1 = fmaf(a.x, w01.z, ax1); ax1 = fmaf(-a.y, w01.w, ax1);
            ay1 = fmaf(a.x, w01.w, ay1); ay1 = fmaf( a.y, w01.z, ay1);
            ax2 = fmaf(a.x, w23.x, ax2); ax2 = fmaf(-a.y, w23.y, ax2);
            ay2 = fmaf(a.x, w23.y, ay2); ay2 = fmaf( a.y, w23.x, ay2);
            ax3 = fmaf(a.x, w23.z, ax3); ax3 = fmaf(-a.y, w23.w, ax3);
            ay3 = fmaf(a.x, w23.w, ay3); ay3 = fmaf( a.y, w23.z, ay3);
        }
        dst[2 * g]     = make_float4(ax0, ay0, ax1, ay1);
        dst[2 * g + 1] = make_float4(ax2, ay2, ax3, ay3);
    }
}

// ---------------------------------------------------------------------------
extern "C" void kernel_launch(void* const* d_in, const int* in_sizes, int n_in,
                              void* d_out, int out_size) {
    const float* x = (const float*)d_in[0];
    float* out = (float*)d_out;
    gram_kernel<<<GB, 256>>>(x);
    cholw_kernel<<<1, 1024>>>();
    apply_kernel<<<MROWS / 64, 64>>>(x, out);
}

// round 7
// speedup vs baseline: 4.5626x; 4.5626x over previous
#include <cuda_runtime.h>

// StrictOrthogonal via Cholesky-QR (all fp32 — fp64 is ~2 ops/cyc/SM on B300):
//   G = X^H X        (148-block split-K partials -> 2-stage deterministic fp32 reduce)
//   G = R^H R        (sqrt-free Cholesky + back-substitution W = R^{-1}, one block)
//   Q = X W          (triangular GEMM, 2 threads/row, column-parity split)

#define MROWS 16384
#define RCOLS 32
#define GB 148                 // gram split-K blocks (one per SM)
#define RPB 111                // rows per gram block (last block: 67)

__device__ float2 g_partials[GB][RCOLS * RCOLS];
__device__ float2 g_p2[4][RCOLS * RCOLS];       // second-stage partials
__device__ float2 g_W[RCOLS * RCOLS];           // W = R^{-1} (upper, zeros below diag)

// ---------------------------------------------------------------------------
// Kernel 1: per-block partial Gram.  Block b handles rows [b*111, ...).
// 256 threads = 4 K-groups x 64 threads; thread owns a 4x4 complex tile,
// accumulating over its ~28 rows from SMEM (SoA planes, float4 loads).
// ---------------------------------------------------------------------------
__global__ void __launch_bounds__(256) gram_kernel(const float* __restrict__ x) {
    __shared__ float4 sbuf4[2048];                 // 32KB
    float*  s_re = reinterpret_cast<float*>(sbuf4);                    // [111][32]
    float*  s_im = s_re + RPB * RCOLS;
    float2* red  = reinterpret_cast<float2*>(sbuf4);                   // 4096 float2

    const int b     = blockIdx.x;
    const int start = b * RPB;
    const int nrows = (start + RPB <= MROWS) ? RPB : (MROWS - start);

    const float4* __restrict__ xr4 =
        reinterpret_cast<const float4*>(x) + (size_t)start * (RCOLS / 2);

    // coalesced float4 load of the tile, split into re/im planes
    for (int t = threadIdx.x; t < nrows * (RCOLS / 2); t += 256) {
        float4 v = xr4[t];                 // two complex values
        s_re[2 * t]     = v.x;  s_im[2 * t]     = v.y;
        s_re[2 * t + 1] = v.z;  s_im[2 * t + 1] = v.w;
    }
    __syncthreads();

    const int t  = threadIdx.x;
    const int g  = t >> 6;          // K-group 0..3 (rows r == g mod 4)
    const int u  = t & 63;
    const int i0 = (u >> 3) * 4;    // 0,4,...,28
    const int j0 = (u & 7) * 4;     // 0,4,...,28

    float accx[4][4], accy[4][4];
    #pragma unroll
    for (int p = 0; p < 4; p++)
        #pragma unroll
        for (int q = 0; q < 4; q++) { accx[p][q] = 0.f; accy[p][q] = 0.f; }

    for (int r = g; r < nrows; r += 4) {
        const float* rr = s_re + r * RCOLS;
        const float* ri = s_im + r * RCOLS;
        float4 arx = *reinterpret_cast<const float4*>(rr + i0);
        float4 ary = *reinterpret_cast<const float4*>(ri + i0);
        float4 brx = *reinterpret_cast<const float4*>(rr + j0);
        float4 bry = *reinterpret_cast<const float4*>(ri + j0);
        const float ax[4] = {arx.x, arx.y, arx.z, arx.w};
        const float ay[4] = {ary.x, ary.y, ary.z, ary.w};
        const float bx[4] = {brx.x, brx.y, brx.z, brx.w};
        const float by[4] = {bry.x, bry.y, bry.z, bry.w};
        #pragma unroll
        for (int p = 0; p < 4; p++)
            #pragma unroll
            for (int q = 0; q < 4; q++) {
                // acc += conj(a_p) * b_q
                accx[p][q] = fmaf(ax[p], bx[q], accx[p][q]);
                accx[p][q] = fmaf(ay[p], by[q], accx[p][q]);
                accy[p][q] = fmaf(ax[p], by[q], accy[p][q]);
                accy[p][q] = fmaf(-ay[p], bx[q], accy[p][q]);
            }
    }
    __syncthreads();   // tile reads done; reuse smem as reduction buffer

    #pragma unroll
    for (int p = 0; p < 4; p++)
        #pragma unroll
        for (int q = 0; q < 4; q++)
            red[g * 1024 + (i0 + p) * 32 + (j0 + q)] = make_float2(accx[p][q], accy[p][q]);
    __syncthreads();

    for (int e = t; e < 1024; e += 256) {
        float2 s0 = red[e], s1 = red[1024 + e], s2 = red[2048 + e], s3 = red[3072 + e];
        g_partials[b][e] = make_float2(s0.x + s1.x + s2.x + s3.x,
                                       s0.y + s1.y + s2.y + s3.y);
    }
}

// ---------------------------------------------------------------------------
// Kernel 2: first-stage reduce. 4096 threads; thread (s, e) sums 37 partials
// for Gram entry e (fp32, fixed order -> deterministic). Spread over 32 SMs.
// ---------------------------------------------------------------------------
__global__ void __launch_bounds__(128) reduce1_kernel() {
    const int n = blockIdx.x * 128 + threadIdx.x;   // 0..4095
    const int e = n & 1023;
    const int s = n >> 10;                          // slice 0..3
    const int b0 = s * 37;                          // 4*37 = 148
    float sx = 0.f, sy = 0.f;
    #pragma unroll 1
    for (int b = 0; b < 37; b++) {
        float2 p = g_partials[b0 + b][e];
        sx += p.x; sy += p.y;
    }
    g_p2[s][e] = make_float2(sx, sy);
}

// ---------------------------------------------------------------------------
// Kernel 3: final reduce (4 slices) -> Cholesky -> W = R^{-1}. One block of
// 1024 threads, thread t = (i = t>>5, j = t&31). All fp32.
// ---------------------------------------------------------------------------
__global__ void __launch_bounds__(1024) cholw_kernel() {
    __shared__ float2 Gs[RCOLS][RCOLS + 1];
    __shared__ float2 Rs[RCOLS][RCOLS];
    __shared__ float2 Bs[RCOLS][RCOLS + 1];
    const int t = threadIdx.x;
    const int i = t >> 5, j = t & 31;

    float2 p0 = g_p2[0][t], p1 = g_p2[1][t], p2 = g_p2[2][t], p3 = g_p2[3][t];
    Gs[i][j] = make_float2((p0.x + p1.x) + (p2.x + p3.x),
                           (p0.y + p1.y) + (p2.y + p3.y));
    Bs[i][j] = make_float2((i == j) ? 1.f : 0.f, 0.f);
    __syncthreads();

    // --- sqrt-free Cholesky (lower triangle), 1 barrier per step ---
    #pragma unroll 1
    for (int k = 0; k < RCOLS; k++) {
        const float invg = 1.f / Gs[k][k].x;
        if (i > k && j > k && j <= i) {
            float2 a = Gs[i][k], c = Gs[j][k];
            float pr = a.x * c.x + a.y * c.y;    // (a * conj(c)).re
            float pi = a.y * c.x - a.x * c.y;    // (a * conj(c)).im
            Gs[i][j].x -= pr * invg;
            Gs[i][j].y -= pi * invg;
        }
        __syncthreads();
    }

    // --- build R (upper): R[i][j] = conj(Gs[j][i]) * rsqrt(D_i), R[i][i]=sqrt(D_i)
    float2 rv = make_float2(0.f, 0.f);
    if (j > i) {
        float2 l = Gs[j][i];
        float  s = rsqrtf(Gs[i][i].x);
        rv = make_float2(l.x * s, -l.y * s);
    } else if (j == i) {
        rv = make_float2(sqrtf(Gs[i][i].x), 0.f);
    }
    Rs[i][j] = rv;
    __syncthreads();

    // --- back-substitution: solve R W = I (W upper incl. diag), 1 barrier/step.
    #pragma unroll 1
    for (int k = RCOLS - 1; k >= 0; k--) {
        const float inv = 1.f / Rs[k][k].x;
        float2 bk = Bs[k][j];
        float2 w  = make_float2(bk.x * inv, bk.y * inv);
        if (i == k)
            g_W[k * RCOLS + j] = (j >= k) ? w : make_float2(0.f, 0.f);
        if (i < k) {
            float2 r = Rs[i][k];
            Bs[i][j].x -= r.x * w.x - r.y * w.y;
            Bs[i][j].y -= r.x * w.y + r.y * w.x;
        }
        __syncthreads();
    }
}

// ---------------------------------------------------------------------------
// Kernel 4: Q = X * W  (W upper triangular, zeros below diag).  TWO threads
// per row: thread parity p owns columns {p, p+2, ..., p+30}, processed in 4
// groups of 4 -> 8 independent FMA chains, 1280 FFMA/thread, 1024 warps total.
// ---------------------------------------------------------------------------
__global__ void __launch_bounds__(128) apply_kernel(const float* __restrict__ x,
                                                    float* __restrict__ out) {
    __shared__ float2 Ws[RCOLS][RCOLS];
    const int t = threadIdx.x;
    for (int e = t; e < RCOLS * RCOLS; e += 128)
        Ws[e >> 5][e & 31] = g_W[e];
    __syncthreads();

    const int p   = t & 1;
    const int row = blockIdx.x * 64 + (t >> 1);
    const float4* __restrict__ src = reinterpret_cast<const float4*>(x) + (size_t)row * 16;
    float2* __restrict__ dst = reinterpret_cast<float2*>(out) + (size_t)row * RCOLS;

    float2 v[RCOLS];
    #pragma unroll
    for (int q = 0; q < 16; q++) {
        float4 f = src[q];
        v[2 * q]     = make_float2(f.x, f.y);
        v[2 * q + 1] = make_float2(f.z, f.w);
    }

    #pragma unroll
    for (int g = 0; g < 4; g++) {
        const int jbase = 8 * g + p;
        float ax[4], ay[4];
        #pragma unroll
        for (int m = 0; m < 4; m++) { ax[m] = 0.f; ay[m] = 0.f; }
        #pragma unroll
        for (int ii = 0; ii < 8 * g + 8; ii++) {   // W zeros below diag handle edges
            const float2 a = v[ii];
            #pragma unroll
            for (int m = 0; m < 4; m++) {
                const float2 w = Ws[ii][jbase + 2 * m];
                ax[m] = fmaf(a.x, w.x, ax[m]); ax[m] = fmaf(-a.y, w.y, ax[m]);
                ay[m] = fmaf(a.x, w.y, ay[m]); ay[m] = fmaf( a.y, w.x, ay[m]);
            }
        }
        #pragma unroll
        for (int m = 0; m < 4; m++)
            dst[jbase + 2 * m] = make_float2(ax[m], ay[m]);
    }
}

// ---------------------------------------------------------------------------
extern "C" void kernel_launch(void* const* d_in, const int* in_sizes, int n_in,
                              void* d_out, int out_size) {
    const float* x = (const float*)d_in[0];
    float* out = (float*)d_out;
    gram_kernel<<<GB, 256>>>(x);
    reduce1_kernel<<<32, 128>>>();
    cholw_kernel<<<1, 1024>>>();
    apply_kernel<<<MROWS / 64, 128>>>(x, out);
}

// round 8
// speedup vs baseline: 4.5885x; 1.0057x over previous
#include <cuda_runtime.h>

// StrictOrthogonal via Cholesky-QR (all fp32):
//   G = X^H X        (256-block split-K partials -> 2-stage deterministic reduce)
//   G = R^H R        (sqrt-free Cholesky + back-substitution W = R^{-1}, one block)
//   Q = X W          (smem-tiled GEMM, W's sub-diagonal zeros absorb triangularity)

#define MROWS 16384
#define RCOLS 32
#define GB 256                 // gram split-K blocks (2 per SM, exact: 256*64=16384)
#define RPB 64                 // rows per gram block

__device__ float2 g_partials[GB][RCOLS * RCOLS];
__device__ float2 g_p2[4][RCOLS * RCOLS];       // second-stage partials
__device__ float2 g_W[RCOLS * RCOLS];           // W = R^{-1} (upper, zeros below diag)

// ---------------------------------------------------------------------------
// Kernel 1: per-block partial Gram over 64 rows.  256 threads = 4 K-groups x
// 64 threads; thread owns a 4x4 complex tile, 16 row-iterations from SMEM.
// ---------------------------------------------------------------------------
__global__ void __launch_bounds__(256) gram_kernel(const float* __restrict__ x) {
    __shared__ float4 sbuf4[2048];                 // 32KB
    float*  s_re = reinterpret_cast<float*>(sbuf4);                    // [64][32]
    float*  s_im = s_re + RPB * RCOLS;
    float2* red  = reinterpret_cast<float2*>(sbuf4);                   // 4096 float2

    const int b = blockIdx.x;
    const float4* __restrict__ xr4 =
        reinterpret_cast<const float4*>(x) + (size_t)b * RPB * (RCOLS / 2);

    // coalesced float4 load (4 per thread), split into re/im planes
    for (int t = threadIdx.x; t < RPB * (RCOLS / 2); t += 256) {
        float4 v = xr4[t];                 // two complex values
        s_re[2 * t]     = v.x;  s_im[2 * t]     = v.y;
        s_re[2 * t + 1] = v.z;  s_im[2 * t + 1] = v.w;
    }
    __syncthreads();

    const int t  = threadIdx.x;
    const int g  = t >> 6;          // K-group 0..3 (rows r == g mod 4)
    const int u  = t & 63;
    const int i0 = (u >> 3) * 4;    // 0,4,...,28
    const int j0 = (u & 7) * 4;     // 0,4,...,28

    float accx[4][4], accy[4][4];
    #pragma unroll
    for (int p = 0; p < 4; p++)
        #pragma unroll
        for (int q = 0; q < 4; q++) { accx[p][q] = 0.f; accy[p][q] = 0.f; }

    #pragma unroll 4
    for (int r = g; r < RPB; r += 4) {
        const float* rr = s_re + r * RCOLS;
        const float* ri = s_im + r * RCOLS;
        float4 arx = *reinterpret_cast<const float4*>(rr + i0);
        float4 ary = *reinterpret_cast<const float4*>(ri + i0);
        float4 brx = *reinterpret_cast<const float4*>(rr + j0);
        float4 bry = *reinterpret_cast<const float4*>(ri + j0);
        const float ax[4] = {arx.x, arx.y, arx.z, arx.w};
        const float ay[4] = {ary.x, ary.y, ary.z, ary.w};
        const float bx[4] = {brx.x, brx.y, brx.z, brx.w};
        const float by[4] = {bry.x, bry.y, bry.z, bry.w};
        #pragma unroll
        for (int p = 0; p < 4; p++)
            #pragma unroll
            for (int q = 0; q < 4; q++) {
                // acc += conj(a_p) * b_q
                accx[p][q] = fmaf(ax[p], bx[q], accx[p][q]);
                accx[p][q] = fmaf(ay[p], by[q], accx[p][q]);
                accy[p][q] = fmaf(ax[p], by[q], accy[p][q]);
                accy[p][q] = fmaf(-ay[p], bx[q], accy[p][q]);
            }
    }
    __syncthreads();   // tile reads done; reuse smem as reduction buffer

    #pragma unroll
    for (int p = 0; p < 4; p++)
        #pragma unroll
        for (int q = 0; q < 4; q++)
            red[g * 1024 + (i0 + p) * 32 + (j0 + q)] = make_float2(accx[p][q], accy[p][q]);
    __syncthreads();

    for (int e = t; e < 1024; e += 256) {
        float2 s0 = red[e], s1 = red[1024 + e], s2 = red[2048 + e], s3 = red[3072 + e];
        g_partials[b][e] = make_float2(s0.x + s1.x + s2.x + s3.x,
                                       s0.y + s1.y + s2.y + s3.y);
    }
}

// ---------------------------------------------------------------------------
// Kernel 2: first-stage reduce. 4096 threads; thread (s, e) sums 64 partials
// for Gram entry e (fp32, fixed order -> deterministic). Spread over 32 SMs.
// ---------------------------------------------------------------------------
__global__ void __launch_bounds__(128) reduce1_kernel() {
    const int n = blockIdx.x * 128 + threadIdx.x;   // 0..4095
    const int e = n & 1023;
    const int s = n >> 10;                          // slice 0..3
    const int b0 = s * (GB / 4);
    float sx0 = 0.f, sy0 = 0.f, sx1 = 0.f, sy1 = 0.f;
    #pragma unroll 2
    for (int b = 0; b < GB / 4; b += 2) {
        float2 p0 = g_partials[b0 + b][e];
        float2 p1 = g_partials[b0 + b + 1][e];
        sx0 += p0.x; sy0 += p0.y;
        sx1 += p1.x; sy1 += p1.y;
    }
    g_p2[s][e] = make_float2(sx0 + sx1, sy0 + sy1);
}

// ---------------------------------------------------------------------------
// Kernel 3: final reduce (4 slices) -> Cholesky -> W = R^{-1}. One block of
// 1024 threads, thread t = (i = t>>5, j = t&31). All fp32.
// ---------------------------------------------------------------------------
__global__ void __launch_bounds__(1024) cholw_kernel() {
    __shared__ float2 Gs[RCOLS][RCOLS + 1];
    __shared__ float2 Rs[RCOLS][RCOLS];
    __shared__ float2 Bs[RCOLS][RCOLS + 1];
    const int t = threadIdx.x;
    const int i = t >> 5, j = t & 31;

    float2 p0 = g_p2[0][t], p1 = g_p2[1][t], p2 = g_p2[2][t], p3 = g_p2[3][t];
    Gs[i][j] = make_float2((p0.x + p1.x) + (p2.x + p3.x),
                           (p0.y + p1.y) + (p2.y + p3.y));
    Bs[i][j] = make_float2((i == j) ? 1.f : 0.f, 0.f);
    __syncthreads();

    // --- sqrt-free Cholesky (lower triangle), 1 barrier per step ---
    #pragma unroll 1
    for (int k = 0; k < RCOLS; k++) {
        const float invg = 1.f / Gs[k][k].x;
        if (i > k && j > k && j <= i) {
            float2 a = Gs[i][k], c = Gs[j][k];
            float pr = a.x * c.x + a.y * c.y;    // (a * conj(c)).re
            float pi = a.y * c.x - a.x * c.y;    // (a * conj(c)).im
            Gs[i][j].x -= pr * invg;
            Gs[i][j].y -= pi * invg;
        }
        __syncthreads();
    }

    // --- build R (upper): R[i][j] = conj(Gs[j][i]) * rsqrt(D_i), R[i][i]=sqrt(D_i)
    float2 rv = make_float2(0.f, 0.f);
    if (j > i) {
        float2 l = Gs[j][i];
        float  s = rsqrtf(Gs[i][i].x);
        rv = make_float2(l.x * s, -l.y * s);
    } else if (j == i) {
        rv = make_float2(sqrtf(Gs[i][i].x), 0.f);
    }
    Rs[i][j] = rv;
    __syncthreads();

    // --- back-substitution: solve R W = I (W upper incl. diag), 1 barrier/step.
    #pragma unroll 1
    for (int k = RCOLS - 1; k >= 0; k--) {
        const float inv = 1.f / Rs[k][k].x;
        float2 bk = Bs[k][j];
        float2 w  = make_float2(bk.x * inv, bk.y * inv);
        if (i == k)
            g_W[k * RCOLS + j] = (j >= k) ? w : make_float2(0.f, 0.f);
        if (i < k) {
            float2 r = Rs[i][k];
            Bs[i][j].x -= r.x * w.x - r.y * w.y;
            Bs[i][j].y -= r.x * w.y + r.y * w.x;
        }
        __syncthreads();
    }
}

// ---------------------------------------------------------------------------
// Kernel 4: Q = X * W.  Smem-tiled GEMM: block = 128 threads = 16 rows x 8
// column-groups of 4.  X tile + W in smem; uniform full ii loop (W zeros
// below the diagonal make triangular handling free).  ~40 regs/thread,
// grid 1024 -> ~28 warps/SM.
// ---------------------------------------------------------------------------
#define AROWS 16
__global__ void __launch_bounds__(128) apply_kernel(const float* __restrict__ x,
                                                    float* __restrict__ out) {
    __shared__ __align__(16) float2 Ws[RCOLS][RCOLS];        // 8KB, unpadded (16B-aligned rows)
    __shared__ float2 Xs[AROWS][RCOLS + 1];                  // padded rows
    const int t = threadIdx.x;

    for (int e = t; e < RCOLS * RCOLS; e += 128)
        Ws[e >> 5][e & 31] = g_W[e];

    const int rowbase = blockIdx.x * AROWS;
    const float4* __restrict__ src =
        reinterpret_cast<const float4*>(x) + (size_t)rowbase * (RCOLS / 2);
    // 16 rows x 16 float4 = 256 float4, 2 per thread, coalesced
    #pragma unroll
    for (int l = 0; l < 2; l++) {
        const int n = t + 128 * l;            // 0..255
        const int r = n >> 4, q = n & 15;     // row, float4 index
        float4 f = src[n];
        Xs[r][2 * q]     = make_float2(f.x, f.y);
        Xs[r][2 * q + 1] = make_float2(f.z, f.w);
    }
    __syncthreads();

    const int r  = t >> 3;          // 0..15  row within tile
    const int c  = t & 7;           // 0..7   column group
    const int j0 = 4 * c;

    float ax0 = 0.f, ay0 = 0.f, ax1 = 0.f, ay1 = 0.f;
    float ax2 = 0.f, ay2 = 0.f, ax3 = 0.f, ay3 = 0.f;
    #pragma unroll
    for (int ii = 0; ii < RCOLS; ii++) {
        const float2 a = Xs[r][ii];
        const float4* wp = reinterpret_cast<const float4*>(&Ws[ii][j0]);
        const float4 w01 = wp[0];             // (W[ii][j0], W[ii][j0+1])
        const float4 w23 = wp[1];             // (W[ii][j0+2], W[ii][j0+3])
        ax0 = fmaf(a.x, w01.x, ax0); ax0 = fmaf(-a.y, w01.y, ax0);
        ay0 = fmaf(a.x, w01.y, ay0); ay0 = fmaf( a.y, w01.x, ay0);
        ax1 = fmaf(a.x, w01.z, ax1); ax1 = fmaf(-a.y, w01.w, ax1);
        ay1 = fmaf(a.x, w01.w, ay1); ay1 = fmaf( a.y, w01.z, ay1);
        ax2 = fmaf(a.x, w23.x, ax2); ax2 = fmaf(-a.y, w23.y, ax2);
        ay2 = fmaf(a.x, w23.y, ay2); ay2 = fmaf( a.y, w23.x, ay2);
        ax3 = fmaf(a.x, w23.z, ax3); ax3 = fmaf(-a.y, w23.w, ax3);
        ay3 = fmaf(a.x, w23.w, ay3); ay3 = fmaf( a.y, w23.z, ay3);
    }

    float4* __restrict__ dst =
        reinterpret_cast<float4*>(out) + (size_t)(rowbase + r) * (RCOLS / 2) + 2 * c;
    dst[0] = make_float4(ax0, ay0, ax1, ay1);
    dst[1] = make_float4(ax2, ay2, ax3, ay3);
}

// ---------------------------------------------------------------------------
extern "C" void kernel_launch(void* const* d_in, const int* in_sizes, int n_in,
                              void* d_out, int out_size) {
    const float* x = (const float*)d_in[0];
    float* out = (float*)d_out;
    gram_kernel<<<GB, 256>>>(x);
    reduce1_kernel<<<32, 128>>>();
    cholw_kernel<<<1, 1024>>>();
    apply_kernel<<<MROWS / AROWS, 128>>>(x, out);
}

// round 9
// speedup vs baseline: 5.7920x; 1.2623x over previous
#include <cuda_runtime.h>

// StrictOrthogonal via Cholesky-QR (all fp32):
//   G = X^H X        (512-block split-K partials -> fused 2-stage reduce)
//   G = R^H R        (reduce + sqrt-free Cholesky + W = R^{-1}, one fused kernel)
//   Q = X W          (register-tiled GEMM, warp-uniform triangular early-out)

#define MROWS 16384
#define RCOLS 32
#define GB 512                 // gram split-K blocks
#define RPB 32                 // rows per gram block (512*32 = 16384)
#define NSLICE 16              // reduce slices (16 * 32 = 512 partials)

__device__ float2 g_partials[GB][RCOLS * RCOLS];
__device__ float2 g_p2[NSLICE][RCOLS * RCOLS];
__device__ float2 g_W[RCOLS * RCOLS];     // W = R^{-1} (upper, zeros below diag)
__device__ int    g_sync;                 // reduce->chol flag (reset by gram)

// ---------------------------------------------------------------------------
// Kernel 1: per-block partial Gram over 32 rows.  256 threads = 4 K-groups x
// 64 threads; thread owns a 4x4 complex tile, 8 row-iterations from SMEM.
// Cross-group reduce done in 4 passes through an 8KB buffer (16KB smem total
// -> ~3.5 blocks/SM at grid 512 -> 28 warps/SM).
// ---------------------------------------------------------------------------
__global__ void __launch_bounds__(256) gram_kernel(const float* __restrict__ x) {
    __shared__ float  s_re[RPB * RCOLS];       // 4KB
    __shared__ float  s_im[RPB * RCOLS];       // 4KB
    __shared__ float2 red[4][256];             // 8KB

    const int t = threadIdx.x;
    const int b = blockIdx.x;
    if (b == 0 && t == 0) g_sync = 0;          // stream-ordered reset for kernel 2

    const float4* __restrict__ xr4 =
        reinterpret_cast<const float4*>(x) + (size_t)b * RPB * (RCOLS / 2);

    // 512 float4 loads, 2 per thread, coalesced; split into re/im planes
    #pragma unroll
    for (int l = 0; l < 2; l++) {
        const int n = t + 256 * l;
        float4 v = xr4[n];
        s_re[2 * n]     = v.x;  s_im[2 * n]     = v.y;
        s_re[2 * n + 1] = v.z;  s_im[2 * n + 1] = v.w;
    }
    __syncthreads();

    const int g  = t >> 6;          // K-group 0..3 (rows r == g mod 4)
    const int u  = t & 63;
    const int i0 = (u >> 3) * 4;    // 0,4,...,28
    const int j0 = (u & 7) * 4;     // 0,4,...,28

    float accx[4][4], accy[4][4];
    #pragma unroll
    for (int p = 0; p < 4; p++)
        #pragma unroll
        for (int q = 0; q < 4; q++) { accx[p][q] = 0.f; accy[p][q] = 0.f; }

    #pragma unroll 4
    for (int it = 0; it < RPB / 4; it++) {
        const int r = g + 4 * it;
        const float* rr = s_re + r * RCOLS;
        const float* ri = s_im + r * RCOLS;
        float4 arx = *reinterpret_cast<const float4*>(rr + i0);
        float4 ary = *reinterpret_cast<const float4*>(ri + i0);
        float4 brx = *reinterpret_cast<const float4*>(rr + j0);
        float4 bry = *reinterpret_cast<const float4*>(ri + j0);
        const float ax[4] = {arx.x, arx.y, arx.z, arx.w};
        const float ay[4] = {ary.x, ary.y, ary.z, ary.w};
        const float bx[4] = {brx.x, brx.y, brx.z, brx.w};
        const float by[4] = {bry.x, bry.y, bry.z, bry.w};
        #pragma unroll
        for (int p = 0; p < 4; p++)
            #pragma unroll
            for (int q = 0; q < 4; q++) {
                // acc += conj(a_p) * b_q
                accx[p][q] = fmaf(ax[p], bx[q], accx[p][q]);
                accx[p][q] = fmaf(ay[p], by[q], accx[p][q]);
                accy[p][q] = fmaf(ax[p], by[q], accy[p][q]);
                accy[p][q] = fmaf(-ay[p], bx[q], accy[p][q]);
            }
    }
    __syncthreads();

    // 4-pass cross-group reduce: pass p covers output rows [8p, 8p+8).
    #pragma unroll 1
    for (int p = 0; p < 4; p++) {
        if ((i0 >> 3) == p) {
            const int il = i0 - 8 * p;                 // 0 or 4
            #pragma unroll
            for (int pp = 0; pp < 4; pp++)
                #pragma unroll
                for (int qq = 0; qq < 4; qq++)
                    red[g][(il + pp) * 32 + j0 + qq] =
                        make_float2(accx[pp][qq], accy[pp][qq]);
        }
        __syncthreads();
        {
            float2 s0 = red[0][t & 255], s1 = red[1][t & 255];
            float2 s2 = red[2][t & 255], s3 = red[3][t & 255];
            g_partials[b][p * 256 + (t & 255)] =
                make_float2((s0.x + s1.x) + (s2.x + s3.x),
                            (s0.y + s1.y) + (s2.y + s3.y));
        }
        __syncthreads();
    }
}

// ---------------------------------------------------------------------------
// Kernel 2 (fused): blocks 0..15 reduce 32 partials each (slice) into g_p2;
// block 16 waits on g_sync, sums the 16 slices, runs Cholesky + W = R^{-1}.
// 17 blocks of 1024 threads -> all resident in wave 1 (no deadlock).
// All sums fixed-order -> deterministic.
// ---------------------------------------------------------------------------
__global__ void __launch_bounds__(1024) redchol_kernel() {
    const int t = threadIdx.x;

    if (blockIdx.x < NSLICE) {
        const int b0 = blockIdx.x * (GB / NSLICE);
        float sx0 = 0.f, sy0 = 0.f, sx1 = 0.f, sy1 = 0.f;
        #pragma unroll 4
        for (int k = 0; k < GB / NSLICE; k += 2) {
            float2 p0 = g_partials[b0 + k][t];
            float2 p1 = g_partials[b0 + k + 1][t];
            sx0 += p0.x; sy0 += p0.y;
            sx1 += p1.x; sy1 += p1.y;
        }
        g_p2[blockIdx.x][t] = make_float2(sx0 + sx1, sy0 + sy1);
        __threadfence();
        __syncthreads();
        if (t == 0) atomicAdd(&g_sync, 1);
        return;
    }

    // --- chol block: wait for all 16 slices ---
    if (t == 0) {
        while (atomicAdd(&g_sync, 0) < NSLICE) { }
        __threadfence();
    }
    __syncthreads();

    __shared__ float2 Gs[RCOLS][RCOLS + 1];
    __shared__ float2 Rs[RCOLS][RCOLS];
    __shared__ float2 Bs[RCOLS][RCOLS + 1];
    const int i = t >> 5, j = t & 31;

    {
        float sx = 0.f, sy = 0.f;
        #pragma unroll
        for (int s = 0; s < NSLICE; s++) {
            float2 p = g_p2[s][t];
            sx += p.x; sy += p.y;
        }
        Gs[i][j] = make_float2(sx, sy);
        Bs[i][j] = make_float2((i == j) ? 1.f : 0.f, 0.f);
    }
    __syncthreads();

    // --- sqrt-free Cholesky (lower triangle), 1 barrier per step ---
    #pragma unroll 1
    for (int k = 0; k < RCOLS; k++) {
        const float invg = 1.f / Gs[k][k].x;
        if (i > k && j > k && j <= i) {
            float2 a = Gs[i][k], c = Gs[j][k];
            float pr = a.x * c.x + a.y * c.y;    // (a * conj(c)).re
            float pi = a.y * c.x - a.x * c.y;    // (a * conj(c)).im
            Gs[i][j].x -= pr * invg;
            Gs[i][j].y -= pi * invg;
        }
        __syncthreads();
    }

    // --- build R (upper): R[i][j] = conj(Gs[j][i]) * rsqrt(D_i), R[i][i]=sqrt(D_i)
    float2 rv = make_float2(0.f, 0.f);
    if (j > i) {
        float2 l = Gs[j][i];
        float  s = rsqrtf(Gs[i][i].x);
        rv = make_float2(l.x * s, -l.y * s);
    } else if (j == i) {
        rv = make_float2(sqrtf(Gs[i][i].x), 0.f);
    }
    Rs[i][j] = rv;
    __syncthreads();

    // --- back-substitution: solve R W = I (W upper incl. diag), 1 barrier/step.
    #pragma unroll 1
    for (int k = RCOLS - 1; k >= 0; k--) {
        const float inv = 1.f / Rs[k][k].x;
        float2 bk = Bs[k][j];
        float2 w  = make_float2(bk.x * inv, bk.y * inv);
        if (i == k)
            g_W[k * RCOLS + j] = (j >= k) ? w : make_float2(0.f, 0.f);
        if (i < k) {
            float2 r = Rs[i][k];
            Bs[i][j].x -= r.x * w.x - r.y * w.y;
            Bs[i][j].y -= r.x * w.y + r.y * w.x;
        }
        __syncthreads();
    }
}

// ---------------------------------------------------------------------------
// Kernel 3: Q = X * W.  Register-tiled: block = 128 threads = 16 row-threads
// (2 rows each: r, r+16) x 8 col-groups (4 cols).  Triangular early-out: col
// group c only needs ii < 4c+4 -> chunk loop ch <= c (44% FLOPs + smem saved;
// warp spans c in {2w, 2w+1} so divergence cost ~0).  48B smem per 32 FFMA.
// ---------------------------------------------------------------------------
#define AROWS 32
__global__ void __launch_bounds__(128) apply_kernel(const float* __restrict__ x,
                                                    float* __restrict__ out) {
    __shared__ __align__(16) float2 Ws[RCOLS][RCOLS];   // 8KB
    __shared__ float2 Xs[AROWS][RCOLS + 1];             // padded rows: stride 33
    const int t = threadIdx.x;

    #pragma unroll
    for (int l = 0; l < 8; l++)
        Ws[(t + 128 * l) >> 5][(t + 128 * l) & 31] = g_W[t + 128 * l];

    const int rowbase = blockIdx.x * AROWS;
    const float4* __restrict__ src =
        reinterpret_cast<const float4*>(x) + (size_t)rowbase * (RCOLS / 2);
    // 32 rows x 16 float4 = 512 float4, 4 per thread, coalesced
    #pragma unroll
    for (int l = 0; l < 4; l++) {
        const int n = t + 128 * l;
        const int r = n >> 4, q = n & 15;
        float4 f = src[n];
        Xs[r][2 * q]     = make_float2(f.x, f.y);
        Xs[r][2 * q + 1] = make_float2(f.z, f.w);
    }
    __syncthreads();

    const int r  = t & 15;          // rows r and r+16
    const int c  = t >> 4;          // column group 0..7
    const int j0 = 4 * c;

    float ax[2][4], ay[2][4];
    #pragma unroll
    for (int m = 0; m < 4; m++) {
        ax[0][m] = 0.f; ay[0][m] = 0.f;
        ax[1][m] = 0.f; ay[1][m] = 0.f;
    }

    #pragma unroll 1
    for (int ch = 0; ch <= c; ch++) {           // triangular: ii < 4c+4
        #pragma unroll
        for (int k = 0; k < 4; k++) {
            const int ii = 4 * ch + k;
            const float2 a0 = Xs[r][ii];
            const float2 a1 = Xs[r + 16][ii];
            const float4 w01 = *reinterpret_cast<const float4*>(&Ws[ii][j0]);
            const float4 w23 = *reinterpret_cast<const float4*>(&Ws[ii][j0 + 2]);
            const float wx[4] = {w01.x, w01.z, w23.x, w23.z};
            const float wy[4] = {w01.y, w01.w, w23.y, w23.w};
            #pragma unroll
            for (int m = 0; m < 4; m++) {
                ax[0][m] = fmaf(a0.x, wx[m], ax[0][m]); ax[0][m] = fmaf(-a0.y, wy[m], ax[0][m]);
                ay[0][m] = fmaf(a0.x, wy[m], ay[0][m]); ay[0][m] = fmaf( a0.y, wx[m], ay[0][m]);
                ax[1][m] = fmaf(a1.x, wx[m], ax[1][m]); ax[1][m] = fmaf(-a1.y, wy[m], ax[1][m]);
                ay[1][m] = fmaf(a1.x, wy[m], ay[1][m]); ay[1][m] = fmaf( a1.y, wx[m], ay[1][m]);
            }
        }
    }

    float4* __restrict__ dst0 =
        reinterpret_cast<float4*>(out) + (size_t)(rowbase + r) * (RCOLS / 2) + 2 * c;
    float4* __restrict__ dst1 =
        reinterpret_cast<float4*>(out) + (size_t)(rowbase + r + 16) * (RCOLS / 2) + 2 * c;
    dst0[0] = make_float4(ax[0][0], ay[0][0], ax[0][1], ay[0][1]);
    dst0[1] = make_float4(ax[0][2], ay[0][2], ax[0][3], ay[0][3]);
    dst1[0] = make_float4(ax[1][0], ay[1][0], ax[1][1], ay[1][1]);
    dst1[1] = make_float4(ax[1][2], ay[1][2], ax[1][3], ay[1][3]);
}

// ---------------------------------------------------------------------------
extern "C" void kernel_launch(void* const* d_in, const int* in_sizes, int n_in,
                              void* d_out, int out_size) {
    const float* x = (const float*)d_in[0];
    float* out = (float*)d_out;
    gram_kernel<<<GB, 256>>>(x);
    redchol_kernel<<<NSLICE + 1, 1024>>>();
    apply_kernel<<<MROWS / AROWS, 128>>>(x, out);
}